// round 14
// baseline (speedup 1.0000x reference)
#include <cuda_runtime.h>
#include <cuda_fp16.h>
#include <cstdint>
#include <math.h>

#define Bc   8
#define Nc   1025
#define Dc   768
#define Hc   12
#define HDc  64
#define E3c  2304
#define Mc   (Bc*Nc)      // 8200
#define MP   8320         // 65*128

#define WSCALE 256.0f
#define INVW   (1.0f/256.0f)

// ---- mma.sync gemm config ----
#define BM 128
#define BN 256
#define BK 32
#define NK (Dc/BK)              // 24
#define ROWB 80
#define ARRA (128*ROWB)         // 10240
#define ARRB (256*ROWB)         // 20480
#define STAGE_BYTES (2*ARRA + 2*ARRB)   // 61440
#define GEMM_SMEM (2*STAGE_BYTES)       // 122880

// ---- attention config ----
#define AQ 128
#define PADR 128
#define KVARR 8192              // 64 rows * 128B
#define KVSTAGE (4*KVARR)
#define QARR 16384              // 128 rows * 128B
#define ATTN_SMEM (2*KVSTAGE + 2*QARR)  // 98304

// ---------------- scratch ----------------
__device__ __half g_ahi[(size_t)MP * Dc];
__device__ __half g_alo[(size_t)MP * Dc];
__device__ __half g_oh [(size_t)MP * Dc];
__device__ __half g_wqhi[(size_t)E3c * Dc];
__device__ __half g_wqlo[(size_t)E3c * Dc];
__device__ __half g_wphi[(size_t)Dc * Dc];
__device__ __half g_wplo[(size_t)Dc * Dc];
#define QKV_ROWS ((size_t)Bc*Hc*Nc + PADR)
__device__ __half g_qh[QKV_ROWS * HDc];
__device__ __half g_ql[QKV_ROWS * HDc];
__device__ __half g_kh[QKV_ROWS * HDc];
__device__ __half g_kl[QKV_ROWS * HDc];
__device__ __half g_vh[QKV_ROWS * HDc];
__device__ __half g_vl[QKV_ROWS * HDc];

// ================= helpers =================
__device__ __forceinline__ uint32_t smem_u32(const void* p) {
    uint32_t a;
    asm("{ .reg .u64 t; cvta.to.shared.u64 t, %1; cvt.u32.u64 %0, t; }"
        : "=r"(a) : "l"(p));
    return a;
}

#define LDM4(r0, r1, r2, r3, addr) \
    asm volatile("ldmatrix.sync.aligned.m8n8.x4.shared.b16 {%0,%1,%2,%3}, [%4];" \
        : "=r"(r0), "=r"(r1), "=r"(r2), "=r"(r3) : "r"(addr))

#define LDM4T(r0, r1, r2, r3, addr) \
    asm volatile("ldmatrix.sync.aligned.m8n8.x4.trans.shared.b16 {%0,%1,%2,%3}, [%4];" \
        : "=r"(r0), "=r"(r1), "=r"(r2), "=r"(r3) : "r"(addr))

#define MMA16816(d, a, b0, b1) \
    asm volatile("mma.sync.aligned.m16n8k16.row.col.f32.f16.f16.f32 " \
        "{%0,%1,%2,%3}, {%4,%5,%6,%7}, {%8,%9}, {%0,%1,%2,%3};" \
        : "+f"((d)[0]), "+f"((d)[1]), "+f"((d)[2]), "+f"((d)[3]) \
        : "r"((a)[0]), "r"((a)[1]), "r"((a)[2]), "r"((a)[3]), "r"(b0), "r"(b1))

__device__ __forceinline__ void cp16(uint32_t dst, const void* src) {
    asm volatile("cp.async.cg.shared.global [%0], [%1], 16;" :: "r"(dst), "l"(src));
}
__device__ __forceinline__ void cp_commit() {
    asm volatile("cp.async.commit_group;" ::: "memory");
}
template<int N>
__device__ __forceinline__ void cp_wait() {
    asm volatile("cp.async.wait_group %0;" :: "n"(N) : "memory");
}

__device__ __forceinline__ uint32_t pack_h2(float x, float y) {
    __half2 h = __floats2half2_rn(x, y);
    return *reinterpret_cast<uint32_t*>(&h);
}
__device__ __forceinline__ void split_pair(float x, float y, uint32_t& hp, uint32_t& lp) {
    __half2 h = __floats2half2_rn(x, y);
    hp = *reinterpret_cast<uint32_t*>(&h);
    float2 hf = __half22float2(h);
    lp = pack_h2(x - hf.x, y - hf.y);
}

__device__ __forceinline__ uint32_t swz(uint32_t base, int row, int chunk) {
    return base + row * 128 + ((chunk ^ (row & 7)) << 4);
}

// ---------------- 1) LayerNorm + fp16 hi/lo split (fused) --------------------
__global__ __launch_bounds__(256) void lnsplit_k(
    const float* __restrict__ x, const float* __restrict__ lg, const float* __restrict__ lb)
{
    const int row = blockIdx.x;
    const float* xr = x + (size_t)row * Dc;
    float v3[3];
    float s = 0.f, s2 = 0.f;
    #pragma unroll
    for (int t = 0; t < 3; t++) {
        float v = xr[threadIdx.x + t * 256];
        v3[t] = v;
        s += v; s2 += v * v;
    }
    #pragma unroll
    for (int o = 16; o; o >>= 1) {
        s  += __shfl_xor_sync(0xffffffffu, s,  o);
        s2 += __shfl_xor_sync(0xffffffffu, s2, o);
    }
    __shared__ float sh[16];
    __shared__ float smu, srs;
    const int w = threadIdx.x >> 5;
    if ((threadIdx.x & 31) == 0) { sh[w] = s; sh[8 + w] = s2; }
    __syncthreads();
    if (threadIdx.x < 32) {
        s  = (threadIdx.x < 8) ? sh[threadIdx.x]     : 0.f;
        s2 = (threadIdx.x < 8) ? sh[8 + threadIdx.x] : 0.f;
        #pragma unroll
        for (int o = 4; o; o >>= 1) {
            s  += __shfl_xor_sync(0xffffffffu, s,  o);
            s2 += __shfl_xor_sync(0xffffffffu, s2, o);
        }
        if (threadIdx.x == 0) {
            float mu  = s  * (1.f / Dc);
            float var = s2 * (1.f / Dc) - mu * mu;
            smu = mu;
            srs = rsqrtf(var + 1e-5f);
        }
    }
    __syncthreads();
    const float mu = smu, rs = srs;
    #pragma unroll
    for (int t = 0; t < 3; t++) {
        int c = threadIdx.x + t * 256;
        float v = (v3[t] - mu) * rs * lg[c] + lb[c];
        __half h = __float2half_rn(v);
        g_ahi[(size_t)row * Dc + c] = h;
        g_alo[(size_t)row * Dc + c] = __float2half_rn(v - __half2float(h));
    }
}

// ---------------- 1b) fused setup: weight splits + pad zeroing ---------------
__global__ void setup_k(const float* __restrict__ wq, const float* __restrict__ wp)
{
    int i = blockIdx.x * 256 + threadIdx.x;
    if (i < E3c * Dc) {
        float v = wq[i] * WSCALE;
        __half h = __float2half_rn(v);
        g_wqhi[i] = h;
        g_wqlo[i] = __float2half_rn(v - __half2float(h));
    }
    if (i < Dc * Dc) {
        float v = wp[i] * WSCALE;
        __half h = __float2half_rn(v);
        g_wphi[i] = h;
        g_wplo[i] = __float2half_rn(v - __half2float(h));
    }
    if (i < PADR * HDc) {
        size_t off = (size_t)Bc * Hc * Nc * HDc + i;
        __half z = __float2half_rn(0.f);
        g_qh[off] = z; g_ql[off] = z;
        g_kh[off] = z; g_kl[off] = z;
        g_vh[off] = z; g_vl[off] = z;
    }
}

// ---------------- 2) mma.sync fp16 GEMM, 128x256 tiles -----------------------
// MODE 0 (3-product): QKV; epilogue: 1/256, RoPE, fp16 split -> g_q/k/v
// MODE 1 (2-product): out = O_fp16 @ (wp*256)^T / 256 + bias
template<int MODE>
__global__ __launch_bounds__(256, 1) void mma_gemm_k(
    const float* __restrict__ bias, float* __restrict__ outp)
{
    const __half* __restrict__ Ahi = (MODE == 0) ? g_ahi : g_oh;
    const __half* __restrict__ Alo = (MODE == 0) ? g_alo : g_oh;
    const __half* __restrict__ Bhi = (MODE == 0) ? g_wqhi : g_wphi;
    const __half* __restrict__ Blo = (MODE == 0) ? g_wqlo : g_wplo;

    extern __shared__ char smem[];
    const uint32_t sb = smem_u32(smem);
    const int tid  = threadIdx.x;
    const int wid  = tid >> 5;
    const int lane = tid & 31;
    const int wm = wid >> 2;            // 0..1, 64 rows
    const int wn = wid & 3;             // 0..3, 64 cols
    const int e0 = blockIdx.x * BN;
    const int m0 = blockIdx.y * BM;

    const __half* gAh = Ahi + (size_t)m0 * Dc;
    const __half* gAl = Alo + (size_t)m0 * Dc;
    const __half* gBh = Bhi + (size_t)e0 * Dc;
    const __half* gBl = Blo + (size_t)e0 * Dc;

    auto load_stage = [&](int s, int k0) {
        const uint32_t stg = sb + s * STAGE_BYTES;
        // A: 128 rows x 4 chunks = 512 cp16 per array -> 2/thread
        #pragma unroll
        for (int i = 0; i < 2; i++) {
            int ci = tid + i * 256;
            int r = ci >> 2, c = ci & 3;
            uint32_t off = r * ROWB + c * 16;
            const size_t go = (size_t)r * Dc + k0 + c * 8;
            cp16(stg + off, gAh + go);
            if (MODE == 0) cp16(stg + ARRA + off, gAl + go);
        }
        // B: 256 rows x 4 chunks = 1024 cp16 per array -> 4/thread
        #pragma unroll
        for (int i = 0; i < 4; i++) {
            int ci = tid + i * 256;
            int r = ci >> 2, c = ci & 3;
            uint32_t off = r * ROWB + c * 16;
            const size_t go = (size_t)r * Dc + k0 + c * 8;
            cp16(stg + 2 * ARRA + off, gBh + go);
            cp16(stg + 2 * ARRA + ARRB + off, gBl + go);
        }
        cp_commit();
    };

    float acc[4][8][4];
    #pragma unroll
    for (int i = 0; i < 4; i++)
        #pragma unroll
        for (int j = 0; j < 8; j++)
            #pragma unroll
            for (int q = 0; q < 4; q++) acc[i][j][q] = 0.f;

    const int a_row   = (lane & 7) + ((lane >> 3) & 1) * 8;
    const int a_chunk = (lane >> 4) & 1;
    const int b_row   = (lane & 7) + ((lane >> 4) & 1) * 8;
    const int b_chunk = (lane >> 3) & 1;

    load_stage(0, 0);

    for (int it = 0; it < NK; it++) {
        if (it + 1 < NK) load_stage((it + 1) & 1, (it + 1) * BK);
        if (it + 1 < NK) cp_wait<1>(); else cp_wait<0>();
        __syncthreads();

        const uint32_t stg = sb + (it & 1) * STAGE_BYTES;
        const uint32_t aHi = stg;
        const uint32_t aLo = stg + ARRA;
        const uint32_t bHi = stg + 2 * ARRA;
        const uint32_t bLo = stg + 2 * ARRA + ARRB;

        #pragma unroll
        for (int k16 = 0; k16 < 2; k16++) {
            uint32_t ah[4][4], al[4][4], bh[4][4], bl[4][4];
            #pragma unroll
            for (int i = 0; i < 4; i++) {
                uint32_t ro = (uint32_t)((wm * 64 + i * 16 + a_row) * ROWB
                                         + (k16 * 2 + a_chunk) * 16);
                LDM4(ah[i][0], ah[i][1], ah[i][2], ah[i][3], aHi + ro);
                if (MODE == 0) {
                    LDM4(al[i][0], al[i][1], al[i][2], al[i][3], aLo + ro);
                }
            }
            #pragma unroll
            for (int j2 = 0; j2 < 4; j2++) {
                uint32_t ro = (uint32_t)((wn * 64 + j2 * 16 + b_row) * ROWB
                                         + (k16 * 2 + b_chunk) * 16);
                LDM4(bh[j2][0], bh[j2][1], bh[j2][2], bh[j2][3], bHi + ro);
                LDM4(bl[j2][0], bl[j2][1], bl[j2][2], bl[j2][3], bLo + ro);
            }
            #pragma unroll
            for (int i = 0; i < 4; i++) {
                #pragma unroll
                for (int j = 0; j < 8; j++) {
                    uint32_t h0 = bh[j >> 1][(j & 1) * 2];
                    uint32_t h1 = bh[j >> 1][(j & 1) * 2 + 1];
                    uint32_t l0 = bl[j >> 1][(j & 1) * 2];
                    uint32_t l1 = bl[j >> 1][(j & 1) * 2 + 1];
                    MMA16816(acc[i][j], ah[i], h0, h1);
                    MMA16816(acc[i][j], ah[i], l0, l1);
                    if (MODE == 0) {
                        MMA16816(acc[i][j], al[i], h0, h1);
                    }
                }
            }
        }
        __syncthreads();
    }

    // ---- epilogue ----
    const int gid = lane >> 2, tig = lane & 3;
    if (MODE == 1) {
        #pragma unroll
        for (int i = 0; i < 4; i++) {
            #pragma unroll
            for (int j = 0; j < 8; j++) {
                int col  = e0 + wn * 64 + j * 8 + tig * 2;
                int row0 = m0 + wm * 64 + i * 16 + gid;
                int row1 = row0 + 8;
                float2 bz = *(const float2*)(bias + col);
                float2 v0 = make_float2(acc[i][j][0] * INVW + bz.x, acc[i][j][1] * INVW + bz.y);
                float2 v1 = make_float2(acc[i][j][2] * INVW + bz.x, acc[i][j][3] * INVW + bz.y);
                if (row0 < Mc) *(float2*)(outp + (size_t)row0 * Dc + col) = v0;
                if (row1 < Mc) *(float2*)(outp + (size_t)row1 * Dc + col) = v1;
            }
        }
    } else {
        const int which = e0 / Dc;           // Dc = 3*256 -> uniform per block
        __half* dH = (which == 0) ? g_qh : (which == 1) ? g_kh : g_vh;
        __half* dL = (which == 0) ? g_ql : (which == 1) ? g_kl : g_vl;
        #pragma unroll
        for (int i = 0; i < 4; i++) {
            #pragma unroll
            for (int j = 0; j < 8; j++) {
                int col = e0 + wn * 64 + j * 8 + tig * 2;
                int rem = col - which * Dc;
                int h = rem >> 6, d = rem & 63;
                int f = (d >> 1) & 15;
                float invf = expf(-(float)f * 0.5756462732485114f);
                #pragma unroll
                for (int rr = 0; rr < 2; rr++) {
                    int row = m0 + wm * 64 + i * 16 + gid + rr * 8;
                    if (row >= Mc) continue;
                    int b = row / Nc, n = row - b * Nc;
                    float x0 = acc[i][j][rr * 2] * INVW, x1 = acc[i][j][rr * 2 + 1] * INVW;
                    float o0, o1;
                    if (which < 2) {
                        int pos = 0;
                        if (n != 0) {
                            int p = n - 1;
                            pos = (d < 32) ? (p >> 5) : (p & 31);
                        }
                        float sn, cs;
                        sincosf((float)pos * invf, &sn, &cs);
                        o0 = x0 * cs - x1 * sn;
                        o1 = x1 * cs + x0 * sn;
                    } else {
                        o0 = x0; o1 = x1;
                    }
                    size_t dst = (((size_t)(b * Hc + h)) * Nc + n) * HDc + d;
                    uint32_t hp, lp;
                    split_pair(o0, o1, hp, lp);
                    *(uint32_t*)(dH + dst) = hp;
                    *(uint32_t*)(dL + dst) = lp;
                }
            }
        }
    }
}

// ---------------- 3) Flash attention, mma.sync fp16 --------------------------
__global__ __launch_bounds__(256, 2) void attn2_k()
{
    extern __shared__ char sm[];
    const uint32_t sb = smem_u32(sm);
    const int tid = threadIdx.x, wid = tid >> 5, lane = tid & 31;
    const int bh = blockIdx.x, q0 = blockIdx.y * AQ;
    const int bI = bh / Hc, hI = bh % Hc;
    const size_t hb = (size_t)bh * Nc * HDc;
    const uint32_t Qh = sb + 2 * KVSTAGE, Ql = Qh + QARR;

    {
        const __half* qhp = g_qh + hb + (size_t)q0 * HDc;
        const __half* qlp = g_ql + hb + (size_t)q0 * HDc;
        #pragma unroll
        for (int t = 0; t < 4; t++) {
            int idx = tid + t * 256;
            int r = idx >> 3, c = idx & 7;
            cp16(swz(Qh, r, c), qhp + (size_t)r * HDc + c * 8);
            cp16(swz(Ql, r, c), qlp + (size_t)r * HDc + c * 8);
        }
        cp_commit();
    }
    auto load_kv = [&](int s, int kt) {
        uint32_t st = sb + s * KVSTAGE;
        const size_t kb = hb + (size_t)kt * 64 * HDc;
        #pragma unroll
        for (int t = 0; t < 2; t++) {
            int idx = tid + t * 256;
            int r = idx >> 3, c = idx & 7;
            size_t go = kb + (size_t)r * HDc + c * 8;
            cp16(swz(st,             r, c), g_kh + go);
            cp16(swz(st +     KVARR, r, c), g_kl + go);
            cp16(swz(st + 2 * KVARR, r, c), g_vh + go);
            cp16(swz(st + 3 * KVARR, r, c), g_vl + go);
        }
        cp_commit();
    };
    load_kv(0, 0);

    cp_wait<1>();
    __syncthreads();
    uint32_t qh[4][4], ql[4][4];
    #pragma unroll
    for (int c = 0; c < 4; c++) {
        int row = wid * 16 + (lane & 15);
        int ch  = c * 2 + (lane >> 4);
        LDM4(qh[c][0], qh[c][1], qh[c][2], qh[c][3], swz(Qh, row, ch));
        LDM4(ql[c][0], ql[c][1], ql[c][2], ql[c][3], swz(Ql, row, ch));
    }

    float out[8][4];
    #pragma unroll
    for (int i = 0; i < 8; i++)
        #pragma unroll
        for (int q = 0; q < 4; q++) out[i][q] = 0.f;
    float m0 = -1e30f, m1 = -1e30f, l0 = 0.f, l1 = 0.f;

    const int NT = (Nc + 63) / 64;   // 17
    for (int kt = 0; kt < NT; kt++) {
        if (kt + 1 < NT) load_kv((kt + 1) & 1, kt + 1);
        if (kt + 1 < NT) cp_wait<1>(); else cp_wait<0>();
        __syncthreads();
        const uint32_t st = sb + (kt & 1) * KVSTAGE;
        const uint32_t Kh = st, Kl = st + KVARR, Vh = st + 2 * KVARR, Vl = st + 3 * KVARR;

        float sac[8][4];
        #pragma unroll
        for (int i = 0; i < 8; i++)
            #pragma unroll
            for (int q = 0; q < 4; q++) sac[i][q] = 0.f;
        #pragma unroll
        for (int c = 0; c < 4; c++) {
            #pragma unroll
            for (int g = 0; g < 4; g++) {
                int row = g * 16 + (lane & 15);
                int ch  = c * 2 + (lane >> 4);
                uint32_t kh0, kh1, kh2, kh3, kl0, kl1, kl2, kl3;
                LDM4(kh0, kh1, kh2, kh3, swz(Kh, row, ch));
                LDM4(kl0, kl1, kl2, kl3, swz(Kl, row, ch));
                MMA16816(sac[2 * g],     qh[c], kh0, kh2);
                MMA16816(sac[2 * g],     qh[c], kl0, kl2);
                MMA16816(sac[2 * g],     ql[c], kh0, kh2);
                MMA16816(sac[2 * g + 1], qh[c], kh1, kh3);
                MMA16816(sac[2 * g + 1], qh[c], kl1, kl3);
                MMA16816(sac[2 * g + 1], ql[c], kh1, kh3);
            }
        }
        const int k0 = kt * 64;
        #pragma unroll
        for (int j = 0; j < 8; j++) {
            sac[j][0] *= 0.125f; sac[j][1] *= 0.125f;
            sac[j][2] *= 0.125f; sac[j][3] *= 0.125f;
            int kc = k0 + j * 8 + 2 * (lane & 3);
            if (kc     >= Nc) { sac[j][0] = -1e30f; sac[j][2] = -1e30f; }
            if (kc + 1 >= Nc) { sac[j][1] = -1e30f; sac[j][3] = -1e30f; }
        }
        float mx0 = -1e30f, mx1 = -1e30f;
        #pragma unroll
        for (int j = 0; j < 8; j++) {
            mx0 = fmaxf(mx0, fmaxf(sac[j][0], sac[j][1]));
            mx1 = fmaxf(mx1, fmaxf(sac[j][2], sac[j][3]));
        }
        mx0 = fmaxf(mx0, __shfl_xor_sync(0xffffffffu, mx0, 1));
        mx0 = fmaxf(mx0, __shfl_xor_sync(0xffffffffu, mx0, 2));
        mx1 = fmaxf(mx1, __shfl_xor_sync(0xffffffffu, mx1, 1));
        mx1 = fmaxf(mx1, __shfl_xor_sync(0xffffffffu, mx1, 2));
        float mn0 = fmaxf(m0, mx0), mn1 = fmaxf(m1, mx1);
        float co0 = __expf(m0 - mn0), co1 = __expf(m1 - mn1);
        m0 = mn0; m1 = mn1;
        float rs0 = 0.f, rs1 = 0.f;
        #pragma unroll
        for (int j = 0; j < 8; j++) {
            sac[j][0] = __expf(sac[j][0] - mn0);
            sac[j][1] = __expf(sac[j][1] - mn0);
            sac[j][2] = __expf(sac[j][2] - mn1);
            sac[j][3] = __expf(sac[j][3] - mn1);
            rs0 += sac[j][0] + sac[j][1];
            rs1 += sac[j][2] + sac[j][3];
        }
        rs0 += __shfl_xor_sync(0xffffffffu, rs0, 1);
        rs0 += __shfl_xor_sync(0xffffffffu, rs0, 2);
        rs1 += __shfl_xor_sync(0xffffffffu, rs1, 1);
        rs1 += __shfl_xor_sync(0xffffffffu, rs1, 2);
        l0 = l0 * co0 + rs0;
        l1 = l1 * co1 + rs1;
        #pragma unroll
        for (int jd = 0; jd < 8; jd++) {
            out[jd][0] *= co0; out[jd][1] *= co0;
            out[jd][2] *= co1; out[jd][3] *= co1;
        }
        #pragma unroll
        for (int kc2 = 0; kc2 < 4; kc2++) {
            uint32_t AH[4];
            AH[0] = pack_h2(sac[2 * kc2][0],     sac[2 * kc2][1]);
            AH[1] = pack_h2(sac[2 * kc2][2],     sac[2 * kc2][3]);
            AH[2] = pack_h2(sac[2 * kc2 + 1][0], sac[2 * kc2 + 1][1]);
            AH[3] = pack_h2(sac[2 * kc2 + 1][2], sac[2 * kc2 + 1][3]);
            #pragma unroll
            for (int jd = 0; jd < 4; jd++) {
                int row = kc2 * 16 + (lane & 15);
                int ch  = jd * 2 + (lane >> 4);
                uint32_t v0, v1, v2, v3, w0, w1, w2, w3;
                LDM4T(v0, v1, v2, v3, swz(Vh, row, ch));
                LDM4T(w0, w1, w2, w3, swz(Vl, row, ch));
                MMA16816(out[2 * jd],     AH, v0, v1);
                MMA16816(out[2 * jd],     AH, w0, w1);
                MMA16816(out[2 * jd + 1], AH, v2, v3);
                MMA16816(out[2 * jd + 1], AH, w2, w3);
            }
        }
        __syncthreads();
    }
    const float inv0 = 1.f / l0, inv1 = 1.f / l1;
    const int r = q0 + wid * 16 + (lane >> 2);
    #pragma unroll
    for (int jd = 0; jd < 8; jd++) {
        int col = hI * 64 + jd * 8 + 2 * (lane & 3);
        if (r < Nc) {
            size_t mi = ((size_t)(bI * Nc + r)) * Dc + col;
            *(uint32_t*)(g_oh + mi) = pack_h2(out[jd][0] * inv0, out[jd][1] * inv0);
        }
        if (r + 8 < Nc) {
            size_t mi = ((size_t)(bI * Nc + r + 8)) * Dc + col;
            *(uint32_t*)(g_oh + mi) = pack_h2(out[jd][2] * inv1, out[jd][3] * inv1);
        }
    }
}

// ---------------- launch ------------------------------------------------------
extern "C" void kernel_launch(void* const* d_in, const int* in_sizes, int n_in,
                              void* d_out, int out_size)
{
    const float* x  = (const float*)d_in[0];
    const float* lg = (const float*)d_in[1];
    const float* lb = (const float*)d_in[2];
    const float* wq = (const float*)d_in[3];
    const float* wp = (const float*)d_in[4];
    const float* bp = (const float*)d_in[5];
    float* out = (float*)d_out;
    (void)in_sizes; (void)n_in; (void)out_size;

    cudaFuncSetAttribute(mma_gemm_k<0>, cudaFuncAttributeMaxDynamicSharedMemorySize, GEMM_SMEM);
    cudaFuncSetAttribute(mma_gemm_k<1>, cudaFuncAttributeMaxDynamicSharedMemorySize, GEMM_SMEM);
    cudaFuncSetAttribute(attn2_k, cudaFuncAttributeMaxDynamicSharedMemorySize, ATTN_SMEM);

    lnsplit_k<<<Mc, 256>>>(x, lg, lb);
    setup_k<<<(E3c * Dc + 255) / 256, 256>>>(wq, wp);
    mma_gemm_k<0><<<dim3(E3c / BN, MP / BM), 256, GEMM_SMEM>>>(nullptr, nullptr);
    attn2_k<<<dim3(Bc * Hc, (Nc + AQ - 1) / AQ), 256, ATTN_SMEM>>>();
    mma_gemm_k<1><<<dim3(Dc / BN, MP / BM), 256, GEMM_SMEM>>>(bp, out);
}

// round 15
// speedup vs baseline: 1.7287x; 1.7287x over previous
#include <cuda_runtime.h>
#include <cuda_fp16.h>
#include <cstdint>
#include <math.h>

#define Bc   8
#define Nc   1025
#define Dc   768
#define Hc   12
#define HDc  64
#define E3c  2304
#define Mc   (Bc*Nc)      // 8200
#define MP   8320         // 65*128

#define WSCALE 256.0f
#define INVW   (1.0f/256.0f)

// ---- mma.sync gemm config (R13 known-good) ----
#define BM 128
#define BN 128
#define BK 32
#define NK (Dc/BK)              // 24
#define ROWB 80
#define ARR_BYTES (128*ROWB)    // 10240
#define STAGE_BYTES (4*ARR_BYTES) // 40960
#define GEMM_SMEM (2*STAGE_BYTES) // 81920

// ---- attention config ----
#define AQ 128
#define PADR 128
#define KVARR 8192              // 64 rows * 128B
#define KVSTAGE (4*KVARR)
#define QARR 16384              // 128 rows * 128B
#define ATTN_SMEM (2*KVSTAGE + 2*QARR)  // 98304

// ---------------- scratch ----------------
__device__ __half g_ahi[(size_t)MP * Dc];
__device__ __half g_alo[(size_t)MP * Dc];
__device__ __half g_oh [(size_t)MP * Dc];
__device__ __half g_wqhi[(size_t)E3c * Dc];
__device__ __half g_wqlo[(size_t)E3c * Dc];
__device__ __half g_wphi[(size_t)Dc * Dc];
__device__ __half g_wplo[(size_t)Dc * Dc];
#define QKV_ROWS ((size_t)Bc*Hc*Nc + PADR)
__device__ __half g_qh[QKV_ROWS * HDc];
__device__ __half g_ql[QKV_ROWS * HDc];
__device__ __half g_kh[QKV_ROWS * HDc];
__device__ __half g_kl[QKV_ROWS * HDc];
__device__ __half g_vh[QKV_ROWS * HDc];
__device__ __half g_vl[QKV_ROWS * HDc];

// ================= helpers =================
__device__ __forceinline__ uint32_t smem_u32(const void* p) {
    uint32_t a;
    asm("{ .reg .u64 t; cvta.to.shared.u64 t, %1; cvt.u32.u64 %0, t; }"
        : "=r"(a) : "l"(p));
    return a;
}

#define LDM4(r0, r1, r2, r3, addr) \
    asm volatile("ldmatrix.sync.aligned.m8n8.x4.shared.b16 {%0,%1,%2,%3}, [%4];" \
        : "=r"(r0), "=r"(r1), "=r"(r2), "=r"(r3) : "r"(addr))

#define LDM4T(r0, r1, r2, r3, addr) \
    asm volatile("ldmatrix.sync.aligned.m8n8.x4.trans.shared.b16 {%0,%1,%2,%3}, [%4];" \
        : "=r"(r0), "=r"(r1), "=r"(r2), "=r"(r3) : "r"(addr))

#define MMA16816(d, a, b0, b1) \
    asm volatile("mma.sync.aligned.m16n8k16.row.col.f32.f16.f16.f32 " \
        "{%0,%1,%2,%3}, {%4,%5,%6,%7}, {%8,%9}, {%0,%1,%2,%3};" \
        : "+f"((d)[0]), "+f"((d)[1]), "+f"((d)[2]), "+f"((d)[3]) \
        : "r"((a)[0]), "r"((a)[1]), "r"((a)[2]), "r"((a)[3]), "r"(b0), "r"(b1))

__device__ __forceinline__ void cp16(uint32_t dst, const void* src) {
    asm volatile("cp.async.cg.shared.global [%0], [%1], 16;" :: "r"(dst), "l"(src));
}
__device__ __forceinline__ void cp_commit() {
    asm volatile("cp.async.commit_group;" ::: "memory");
}
template<int N>
__device__ __forceinline__ void cp_wait() {
    asm volatile("cp.async.wait_group %0;" :: "n"(N) : "memory");
}

__device__ __forceinline__ uint32_t pack_h2(float x, float y) {
    __half2 h = __floats2half2_rn(x, y);
    return *reinterpret_cast<uint32_t*>(&h);
}
__device__ __forceinline__ void split_pair(float x, float y, uint32_t& hp, uint32_t& lp) {
    __half2 h = __floats2half2_rn(x, y);
    hp = *reinterpret_cast<uint32_t*>(&h);
    float2 hf = __half22float2(h);
    lp = pack_h2(x - hf.x, y - hf.y);
}

__device__ __forceinline__ uint32_t swz(uint32_t base, int row, int chunk) {
    return base + row * 128 + ((chunk ^ (row & 7)) << 4);
}

// ---------------- 1) LayerNorm + fp16 hi/lo split (fused) --------------------
__global__ __launch_bounds__(256) void lnsplit_k(
    const float* __restrict__ x, const float* __restrict__ lg, const float* __restrict__ lb)
{
    const int row = blockIdx.x;
    const float* xr = x + (size_t)row * Dc;
    float v3[3];
    float s = 0.f, s2 = 0.f;
    #pragma unroll
    for (int t = 0; t < 3; t++) {
        float v = xr[threadIdx.x + t * 256];
        v3[t] = v;
        s += v; s2 += v * v;
    }
    #pragma unroll
    for (int o = 16; o; o >>= 1) {
        s  += __shfl_xor_sync(0xffffffffu, s,  o);
        s2 += __shfl_xor_sync(0xffffffffu, s2, o);
    }
    __shared__ float sh[16];
    __shared__ float smu, srs;
    const int w = threadIdx.x >> 5;
    if ((threadIdx.x & 31) == 0) { sh[w] = s; sh[8 + w] = s2; }
    __syncthreads();
    if (threadIdx.x < 32) {
        s  = (threadIdx.x < 8) ? sh[threadIdx.x]     : 0.f;
        s2 = (threadIdx.x < 8) ? sh[8 + threadIdx.x] : 0.f;
        #pragma unroll
        for (int o = 4; o; o >>= 1) {
            s  += __shfl_xor_sync(0xffffffffu, s,  o);
            s2 += __shfl_xor_sync(0xffffffffu, s2, o);
        }
        if (threadIdx.x == 0) {
            float mu  = s  * (1.f / Dc);
            float var = s2 * (1.f / Dc) - mu * mu;
            smu = mu;
            srs = rsqrtf(var + 1e-5f);
        }
    }
    __syncthreads();
    const float mu = smu, rs = srs;
    #pragma unroll
    for (int t = 0; t < 3; t++) {
        int c = threadIdx.x + t * 256;
        float v = (v3[t] - mu) * rs * lg[c] + lb[c];
        __half h = __float2half_rn(v);
        g_ahi[(size_t)row * Dc + c] = h;
        g_alo[(size_t)row * Dc + c] = __float2half_rn(v - __half2float(h));
    }
}

// ---------------- 1b) fused setup: weight splits + pad zeroing ---------------
__global__ void setup_k(const float* __restrict__ wq, const float* __restrict__ wp)
{
    int i = blockIdx.x * 256 + threadIdx.x;
    if (i < E3c * Dc) {
        float v = wq[i] * WSCALE;
        __half h = __float2half_rn(v);
        g_wqhi[i] = h;
        g_wqlo[i] = __float2half_rn(v - __half2float(h));
    }
    if (i < Dc * Dc) {
        float v = wp[i] * WSCALE;
        __half h = __float2half_rn(v);
        g_wphi[i] = h;
        g_wplo[i] = __float2half_rn(v - __half2float(h));
    }
    if (i < PADR * HDc) {
        size_t off = (size_t)Bc * Hc * Nc * HDc + i;
        __half z = __float2half_rn(0.f);
        g_qh[off] = z; g_ql[off] = z;
        g_kh[off] = z; g_kl[off] = z;
        g_vh[off] = z; g_vl[off] = z;
    }
}

// ---------------- 2) mma.sync fp16 GEMM, 128x128, 2 CTA/SM (R13) -------------
// MODE 0 (3-product): QKV; epilogue: 1/256, RoPE, fp16 split -> g_q/k/v
// MODE 1 (2-product): out = O_fp16 @ (wp*256)^T / 256 + bias
template<int MODE>
__global__ __launch_bounds__(256, 2) void mma_gemm_k(
    const float* __restrict__ bias, float* __restrict__ outp)
{
    const __half* __restrict__ Ahi = (MODE == 0) ? g_ahi : g_oh;
    const __half* __restrict__ Alo = (MODE == 0) ? g_alo : g_oh;   // unused if MODE 1
    const __half* __restrict__ Bhi = (MODE == 0) ? g_wqhi : g_wphi;
    const __half* __restrict__ Blo = (MODE == 0) ? g_wqlo : g_wplo;

    extern __shared__ char smem[];
    const uint32_t sb = smem_u32(smem);
    const int tid  = threadIdx.x;
    const int wid  = tid >> 5;
    const int lane = tid & 31;
    const int wm = wid >> 2;
    const int wn = wid & 3;
    const int e0 = blockIdx.x * BN;
    const int m0 = blockIdx.y * BM;

    const __half* gA[4] = {
        Ahi + (size_t)m0 * Dc, Alo + (size_t)m0 * Dc,
        Bhi + (size_t)e0 * Dc, Blo + (size_t)e0 * Dc };

    auto load_stage = [&](int s, int k0) {
        const uint32_t stg = sb + s * STAGE_BYTES;
        #pragma unroll
        for (int arr = 0; arr < 4; arr++) {
            if (MODE == 1 && arr == 1) continue;
            #pragma unroll
            for (int i = 0; i < 2; i++) {
                int ci = tid + i * 256;
                int r = ci >> 2, c = ci & 3;
                cp16(stg + arr * ARR_BYTES + r * ROWB + c * 16,
                     gA[arr] + (size_t)r * Dc + k0 + c * 8);
            }
        }
        cp_commit();
    };

    float acc[4][4][4];
    #pragma unroll
    for (int i = 0; i < 4; i++)
        #pragma unroll
        for (int j = 0; j < 4; j++)
            #pragma unroll
            for (int q = 0; q < 4; q++) acc[i][j][q] = 0.f;

    const int a_row   = (lane & 7) + ((lane >> 3) & 1) * 8;
    const int a_chunk = (lane >> 4) & 1;
    const int b_row   = (lane & 7) + ((lane >> 4) & 1) * 8;
    const int b_chunk = (lane >> 3) & 1;

    load_stage(0, 0);

    for (int it = 0; it < NK; it++) {
        if (it + 1 < NK) load_stage((it + 1) & 1, (it + 1) * BK);
        if (it + 1 < NK) cp_wait<1>(); else cp_wait<0>();
        __syncthreads();

        const uint32_t stg = sb + (it & 1) * STAGE_BYTES;
        const uint32_t aHi = stg;
        const uint32_t aLo = stg + ARR_BYTES;
        const uint32_t bHi = stg + 2 * ARR_BYTES;
        const uint32_t bLo = stg + 3 * ARR_BYTES;

        #pragma unroll
        for (int k16 = 0; k16 < 2; k16++) {
            uint32_t ah[4][4], al[4][4], bh[2][4], bl[2][4];
            #pragma unroll
            for (int i = 0; i < 4; i++) {
                uint32_t ro = (uint32_t)((wm * 64 + i * 16 + a_row) * ROWB
                                         + (k16 * 2 + a_chunk) * 16);
                LDM4(ah[i][0], ah[i][1], ah[i][2], ah[i][3], aHi + ro);
                if (MODE == 0) {
                    LDM4(al[i][0], al[i][1], al[i][2], al[i][3], aLo + ro);
                }
            }
            #pragma unroll
            for (int j2 = 0; j2 < 2; j2++) {
                uint32_t ro = (uint32_t)((wn * 32 + j2 * 16 + b_row) * ROWB
                                         + (k16 * 2 + b_chunk) * 16);
                LDM4(bh[j2][0], bh[j2][1], bh[j2][2], bh[j2][3], bHi + ro);
                LDM4(bl[j2][0], bl[j2][1], bl[j2][2], bl[j2][3], bLo + ro);
            }
            #pragma unroll
            for (int i = 0; i < 4; i++) {
                #pragma unroll
                for (int j = 0; j < 4; j++) {
                    uint32_t h0 = bh[j >> 1][(j & 1) * 2];
                    uint32_t h1 = bh[j >> 1][(j & 1) * 2 + 1];
                    uint32_t l0 = bl[j >> 1][(j & 1) * 2];
                    uint32_t l1 = bl[j >> 1][(j & 1) * 2 + 1];
                    MMA16816(acc[i][j], ah[i], h0, h1);
                    MMA16816(acc[i][j], ah[i], l0, l1);
                    if (MODE == 0) {
                        MMA16816(acc[i][j], al[i], h0, h1);
                    }
                }
            }
        }
        __syncthreads();
    }

    // ---- epilogue ----
    const int gid = lane >> 2, tig = lane & 3;
    if (MODE == 1) {
        #pragma unroll
        for (int i = 0; i < 4; i++) {
            #pragma unroll
            for (int j = 0; j < 4; j++) {
                int col  = e0 + wn * 32 + j * 8 + tig * 2;
                int row0 = m0 + wm * 64 + i * 16 + gid;
                int row1 = row0 + 8;
                float2 bz = *(const float2*)(bias + col);
                float2 v0 = make_float2(acc[i][j][0] * INVW + bz.x, acc[i][j][1] * INVW + bz.y);
                float2 v1 = make_float2(acc[i][j][2] * INVW + bz.x, acc[i][j][3] * INVW + bz.y);
                if (row0 < Mc) *(float2*)(outp + (size_t)row0 * Dc + col) = v0;
                if (row1 < Mc) *(float2*)(outp + (size_t)row1 * Dc + col) = v1;
            }
        }
    } else {
        const int which = e0 / Dc;
        __half* dH = (which == 0) ? g_qh : (which == 1) ? g_kh : g_vh;
        __half* dL = (which == 0) ? g_ql : (which == 1) ? g_kl : g_vl;
        #pragma unroll
        for (int i = 0; i < 4; i++) {
            #pragma unroll
            for (int j = 0; j < 4; j++) {
                int col = e0 + wn * 32 + j * 8 + tig * 2;
                int rem = col - which * Dc;
                int h = rem >> 6, d = rem & 63;
                int f = (d >> 1) & 15;
                float invf = expf(-(float)f * 0.5756462732485114f);
                #pragma unroll
                for (int rr = 0; rr < 2; rr++) {
                    int row = m0 + wm * 64 + i * 16 + gid + rr * 8;
                    if (row >= Mc) continue;
                    int b = row / Nc, n = row - b * Nc;
                    float x0 = acc[i][j][rr * 2] * INVW, x1 = acc[i][j][rr * 2 + 1] * INVW;
                    float o0, o1;
                    if (which < 2) {
                        int pos = 0;
                        if (n != 0) {
                            int p = n - 1;
                            pos = (d < 32) ? (p >> 5) : (p & 31);
                        }
                        float sn, cs;
                        sincosf((float)pos * invf, &sn, &cs);
                        o0 = x0 * cs - x1 * sn;
                        o1 = x1 * cs + x0 * sn;
                    } else {
                        o0 = x0; o1 = x1;
                    }
                    size_t dst = (((size_t)(b * Hc + h)) * Nc + n) * HDc + d;
                    uint32_t hp, lp;
                    split_pair(o0, o1, hp, lp);
                    *(uint32_t*)(dH + dst) = hp;
                    *(uint32_t*)(dL + dst) = lp;
                }
            }
        }
    }
}

// ---------------- 3) Flash attention, mma.sync fp16 (R13, 1 CTA/SM) ----------
__global__ __launch_bounds__(256, 1) void attn2_k()
{
    extern __shared__ char sm[];
    const uint32_t sb = smem_u32(sm);
    const int tid = threadIdx.x, wid = tid >> 5, lane = tid & 31;
    const int bh = blockIdx.x, q0 = blockIdx.y * AQ;
    const int bI = bh / Hc, hI = bh % Hc;
    const size_t hb = (size_t)bh * Nc * HDc;
    const uint32_t Qh = sb + 2 * KVSTAGE, Ql = Qh + QARR;

    {
        const __half* qhp = g_qh + hb + (size_t)q0 * HDc;
        const __half* qlp = g_ql + hb + (size_t)q0 * HDc;
        #pragma unroll
        for (int t = 0; t < 4; t++) {
            int idx = tid + t * 256;
            int r = idx >> 3, c = idx & 7;
            cp16(swz(Qh, r, c), qhp + (size_t)r * HDc + c * 8);
            cp16(swz(Ql, r, c), qlp + (size_t)r * HDc + c * 8);
        }
        cp_commit();
    }
    auto load_kv = [&](int s, int kt) {
        uint32_t st = sb + s * KVSTAGE;
        const size_t kb = hb + (size_t)kt * 64 * HDc;
        #pragma unroll
        for (int t = 0; t < 2; t++) {
            int idx = tid + t * 256;
            int r = idx >> 3, c = idx & 7;
            size_t go = kb + (size_t)r * HDc + c * 8;
            cp16(swz(st,             r, c), g_kh + go);
            cp16(swz(st +     KVARR, r, c), g_kl + go);
            cp16(swz(st + 2 * KVARR, r, c), g_vh + go);
            cp16(swz(st + 3 * KVARR, r, c), g_vl + go);
        }
        cp_commit();
    };
    load_kv(0, 0);

    cp_wait<1>();
    __syncthreads();
    uint32_t qh[4][4], ql[4][4];
    #pragma unroll
    for (int c = 0; c < 4; c++) {
        int row = wid * 16 + (lane & 15);
        int ch  = c * 2 + (lane >> 4);
        LDM4(qh[c][0], qh[c][1], qh[c][2], qh[c][3], swz(Qh, row, ch));
        LDM4(ql[c][0], ql[c][1], ql[c][2], ql[c][3], swz(Ql, row, ch));
    }

    float out[8][4];
    #pragma unroll
    for (int i = 0; i < 8; i++)
        #pragma unroll
        for (int q = 0; q < 4; q++) out[i][q] = 0.f;
    float m0 = -1e30f, m1 = -1e30f, l0 = 0.f, l1 = 0.f;

    const int NT = (Nc + 63) / 64;   // 17
    for (int kt = 0; kt < NT; kt++) {
        if (kt + 1 < NT) load_kv((kt + 1) & 1, kt + 1);
        if (kt + 1 < NT) cp_wait<1>(); else cp_wait<0>();
        __syncthreads();
        const uint32_t st = sb + (kt & 1) * KVSTAGE;
        const uint32_t Kh = st, Kl = st + KVARR, Vh = st + 2 * KVARR, Vl = st + 3 * KVARR;

        float sac[8][4];
        #pragma unroll
        for (int i = 0; i < 8; i++)
            #pragma unroll
            for (int q = 0; q < 4; q++) sac[i][q] = 0.f;
        #pragma unroll
        for (int c = 0; c < 4; c++) {
            #pragma unroll
            for (int g = 0; g < 4; g++) {
                int row = g * 16 + (lane & 15);
                int ch  = c * 2 + (lane >> 4);
                uint32_t kh0, kh1, kh2, kh3, kl0, kl1, kl2, kl3;
                LDM4(kh0, kh1, kh2, kh3, swz(Kh, row, ch));
                LDM4(kl0, kl1, kl2, kl3, swz(Kl, row, ch));
                MMA16816(sac[2 * g],     qh[c], kh0, kh2);
                MMA16816(sac[2 * g],     qh[c], kl0, kl2);
                MMA16816(sac[2 * g],     ql[c], kh0, kh2);
                MMA16816(sac[2 * g + 1], qh[c], kh1, kh3);
                MMA16816(sac[2 * g + 1], qh[c], kl1, kl3);
                MMA16816(sac[2 * g + 1], ql[c], kh1, kh3);
            }
        }
        const int k0 = kt * 64;
        #pragma unroll
        for (int j = 0; j < 8; j++) {
            sac[j][0] *= 0.125f; sac[j][1] *= 0.125f;
            sac[j][2] *= 0.125f; sac[j][3] *= 0.125f;
            int kc = k0 + j * 8 + 2 * (lane & 3);
            if (kc     >= Nc) { sac[j][0] = -1e30f; sac[j][2] = -1e30f; }
            if (kc + 1 >= Nc) { sac[j][1] = -1e30f; sac[j][3] = -1e30f; }
        }
        float mx0 = -1e30f, mx1 = -1e30f;
        #pragma unroll
        for (int j = 0; j < 8; j++) {
            mx0 = fmaxf(mx0, fmaxf(sac[j][0], sac[j][1]));
            mx1 = fmaxf(mx1, fmaxf(sac[j][2], sac[j][3]));
        }
        mx0 = fmaxf(mx0, __shfl_xor_sync(0xffffffffu, mx0, 1));
        mx0 = fmaxf(mx0, __shfl_xor_sync(0xffffffffu, mx0, 2));
        mx1 = fmaxf(mx1, __shfl_xor_sync(0xffffffffu, mx1, 1));
        mx1 = fmaxf(mx1, __shfl_xor_sync(0xffffffffu, mx1, 2));
        float mn0 = fmaxf(m0, mx0), mn1 = fmaxf(m1, mx1);
        float co0 = __expf(m0 - mn0), co1 = __expf(m1 - mn1);
        m0 = mn0; m1 = mn1;
        float rs0 = 0.f, rs1 = 0.f;
        #pragma unroll
        for (int j = 0; j < 8; j++) {
            sac[j][0] = __expf(sac[j][0] - mn0);
            sac[j][1] = __expf(sac[j][1] - mn0);
            sac[j][2] = __expf(sac[j][2] - mn1);
            sac[j][3] = __expf(sac[j][3] - mn1);
            rs0 += sac[j][0] + sac[j][1];
            rs1 += sac[j][2] + sac[j][3];
        }
        rs0 += __shfl_xor_sync(0xffffffffu, rs0, 1);
        rs0 += __shfl_xor_sync(0xffffffffu, rs0, 2);
        rs1 += __shfl_xor_sync(0xffffffffu, rs1, 1);
        rs1 += __shfl_xor_sync(0xffffffffu, rs1, 2);
        l0 = l0 * co0 + rs0;
        l1 = l1 * co1 + rs1;
        #pragma unroll
        for (int jd = 0; jd < 8; jd++) {
            out[jd][0] *= co0; out[jd][1] *= co0;
            out[jd][2] *= co1; out[jd][3] *= co1;
        }
        #pragma unroll
        for (int kc2 = 0; kc2 < 4; kc2++) {
            uint32_t AH[4];
            AH[0] = pack_h2(sac[2 * kc2][0],     sac[2 * kc2][1]);
            AH[1] = pack_h2(sac[2 * kc2][2],     sac[2 * kc2][3]);
            AH[2] = pack_h2(sac[2 * kc2 + 1][0], sac[2 * kc2 + 1][1]);
            AH[3] = pack_h2(sac[2 * kc2 + 1][2], sac[2 * kc2 + 1][3]);
            #pragma unroll
            for (int jd = 0; jd < 4; jd++) {
                int row = kc2 * 16 + (lane & 15);
                int ch  = jd * 2 + (lane >> 4);
                uint32_t v0, v1, v2, v3, w0, w1, w2, w3;
                LDM4T(v0, v1, v2, v3, swz(Vh, row, ch));
                LDM4T(w0, w1, w2, w3, swz(Vl, row, ch));
                MMA16816(out[2 * jd],     AH, v0, v1);
                MMA16816(out[2 * jd],     AH, w0, w1);
                MMA16816(out[2 * jd + 1], AH, v2, v3);
                MMA16816(out[2 * jd + 1], AH, w2, w3);
            }
        }
        __syncthreads();
    }
    const float inv0 = 1.f / l0, inv1 = 1.f / l1;
    const int r = q0 + wid * 16 + (lane >> 2);
    #pragma unroll
    for (int jd = 0; jd < 8; jd++) {
        int col = hI * 64 + jd * 8 + 2 * (lane & 3);
        if (r < Nc) {
            size_t mi = ((size_t)(bI * Nc + r)) * Dc + col;
            *(uint32_t*)(g_oh + mi) = pack_h2(out[jd][0] * inv0, out[jd][1] * inv0);
        }
        if (r + 8 < Nc) {
            size_t mi = ((size_t)(bI * Nc + r + 8)) * Dc + col;
            *(uint32_t*)(g_oh + mi) = pack_h2(out[jd][2] * inv1, out[jd][3] * inv1);
        }
    }
}

// ---------------- launch ------------------------------------------------------
extern "C" void kernel_launch(void* const* d_in, const int* in_sizes, int n_in,
                              void* d_out, int out_size)
{
    const float* x  = (const float*)d_in[0];
    const float* lg = (const float*)d_in[1];
    const float* lb = (const float*)d_in[2];
    const float* wq = (const float*)d_in[3];
    const float* wp = (const float*)d_in[4];
    const float* bp = (const float*)d_in[5];
    float* out = (float*)d_out;
    (void)in_sizes; (void)n_in; (void)out_size;

    cudaFuncSetAttribute(mma_gemm_k<0>, cudaFuncAttributeMaxDynamicSharedMemorySize, GEMM_SMEM);
    cudaFuncSetAttribute(mma_gemm_k<1>, cudaFuncAttributeMaxDynamicSharedMemorySize, GEMM_SMEM);
    cudaFuncSetAttribute(attn2_k, cudaFuncAttributeMaxDynamicSharedMemorySize, ATTN_SMEM);

    lnsplit_k<<<Mc, 256>>>(x, lg, lb);
    setup_k<<<(E3c * Dc + 255) / 256, 256>>>(wq, wp);
    mma_gemm_k<0><<<dim3(E3c / BN, MP / BM), 256, GEMM_SMEM>>>(nullptr, nullptr);
    attn2_k<<<dim3(Bc * Hc, (Nc + AQ - 1) / AQ), 256, ATTN_SMEM>>>();
    mma_gemm_k<1><<<dim3(Dc / BN, MP / BM), 256, GEMM_SMEM>>>(bp, out);
}

// round 17
// speedup vs baseline: 1.7484x; 1.0114x over previous
#include <cuda_runtime.h>
#include <cuda_fp16.h>
#include <cstdint>
#include <math.h>

#define Bc   8
#define Nc   1025
#define Dc   768
#define Hc   12
#define HDc  64
#define E3c  2304
#define Mc   (Bc*Nc)      // 8200
#define MP   8320         // 65*128

#define WSCALE 256.0f
#define INVW   (1.0f/256.0f)

// ---- mma.sync gemm config (R13 known-good) ----
#define BM 128
#define BN 128
#define BK 32
#define NK (Dc/BK)              // 24
#define ROWB 80
#define ARR_BYTES (128*ROWB)    // 10240
#define STAGE_BYTES (4*ARR_BYTES) // 40960
#define GEMM_SMEM (2*STAGE_BYTES) // 81920

// ---- attention config ----
#define ATHREADS 384
#define AQ 192
#define PADR 192
#define KVARR 8192              // 64 rows * 128B
#define KVSTAGE (4*KVARR)       // 32768
#define QARR (AQ*128)           // 24576
#define ATTN_SMEM (3*KVSTAGE + 2*QARR)  // 147456

// ---------------- scratch ----------------
__device__ __half g_ahi[(size_t)MP * Dc];
__device__ __half g_alo[(size_t)MP * Dc];
__device__ __half g_oh [(size_t)MP * Dc];
__device__ __half g_wqhi[(size_t)E3c * Dc];
__device__ __half g_wqlo[(size_t)E3c * Dc];
__device__ __half g_wphi[(size_t)Dc * Dc];
__device__ __half g_wplo[(size_t)Dc * Dc];
#define QKV_ROWS ((size_t)Bc*Hc*Nc + PADR)
__device__ __half g_qh[QKV_ROWS * HDc];
__device__ __half g_ql[QKV_ROWS * HDc];
__device__ __half g_kh[QKV_ROWS * HDc];
__device__ __half g_kl[QKV_ROWS * HDc];
__device__ __half g_vh[QKV_ROWS * HDc];
__device__ __half g_vl[QKV_ROWS * HDc];

// ================= helpers =================
__device__ __forceinline__ uint32_t smem_u32(const void* p) {
    uint32_t a;
    asm("{ .reg .u64 t; cvta.to.shared.u64 t, %1; cvt.u32.u64 %0, t; }"
        : "=r"(a) : "l"(p));
    return a;
}

#define LDM4(r0, r1, r2, r3, addr) \
    asm volatile("ldmatrix.sync.aligned.m8n8.x4.shared.b16 {%0,%1,%2,%3}, [%4];" \
        : "=r"(r0), "=r"(r1), "=r"(r2), "=r"(r3) : "r"(addr))

#define LDM4T(r0, r1, r2, r3, addr) \
    asm volatile("ldmatrix.sync.aligned.m8n8.x4.trans.shared.b16 {%0,%1,%2,%3}, [%4];" \
        : "=r"(r0), "=r"(r1), "=r"(r2), "=r"(r3) : "r"(addr))

#define MMA16816(d, a, b0, b1) \
    asm volatile("mma.sync.aligned.m16n8k16.row.col.f32.f16.f16.f32 " \
        "{%0,%1,%2,%3}, {%4,%5,%6,%7}, {%8,%9}, {%0,%1,%2,%3};" \
        : "+f"((d)[0]), "+f"((d)[1]), "+f"((d)[2]), "+f"((d)[3]) \
        : "r"((a)[0]), "r"((a)[1]), "r"((a)[2]), "r"((a)[3]), "r"(b0), "r"(b1))

__device__ __forceinline__ void cp16(uint32_t dst, const void* src) {
    asm volatile("cp.async.cg.shared.global [%0], [%1], 16;" :: "r"(dst), "l"(src));
}
__device__ __forceinline__ void cp_commit() {
    asm volatile("cp.async.commit_group;" ::: "memory");
}
template<int N>
__device__ __forceinline__ void cp_wait() {
    asm volatile("cp.async.wait_group %0;" :: "n"(N) : "memory");
}

__device__ __forceinline__ uint32_t pack_h2(float x, float y) {
    __half2 h = __floats2half2_rn(x, y);
    return *reinterpret_cast<uint32_t*>(&h);
}
__device__ __forceinline__ void split_pair(float x, float y, uint32_t& hp, uint32_t& lp) {
    __half2 h = __floats2half2_rn(x, y);
    hp = *reinterpret_cast<uint32_t*>(&h);
    float2 hf = __half22float2(h);
    lp = pack_h2(x - hf.x, y - hf.y);
}

__device__ __forceinline__ uint32_t swz(uint32_t base, int row, int chunk) {
    return base + row * 128 + ((chunk ^ (row & 7)) << 4);
}

// ---------------- 1) LayerNorm + fp16 hi/lo split (fused) --------------------
__global__ __launch_bounds__(256) void lnsplit_k(
    const float* __restrict__ x, const float* __restrict__ lg, const float* __restrict__ lb)
{
    const int row = blockIdx.x;
    const float* xr = x + (size_t)row * Dc;
    float v3[3];
    float s = 0.f, s2 = 0.f;
    #pragma unroll
    for (int t = 0; t < 3; t++) {
        float v = xr[threadIdx.x + t * 256];
        v3[t] = v;
        s += v; s2 += v * v;
    }
    #pragma unroll
    for (int o = 16; o; o >>= 1) {
        s  += __shfl_xor_sync(0xffffffffu, s,  o);
        s2 += __shfl_xor_sync(0xffffffffu, s2, o);
    }
    __shared__ float sh[16];
    __shared__ float smu, srs;
    const int w = threadIdx.x >> 5;
    if ((threadIdx.x & 31) == 0) { sh[w] = s; sh[8 + w] = s2; }
    __syncthreads();
    if (threadIdx.x < 32) {
        s  = (threadIdx.x < 8) ? sh[threadIdx.x]     : 0.f;
        s2 = (threadIdx.x < 8) ? sh[8 + threadIdx.x] : 0.f;
        #pragma unroll
        for (int o = 4; o; o >>= 1) {
            s  += __shfl_xor_sync(0xffffffffu, s,  o);
            s2 += __shfl_xor_sync(0xffffffffu, s2, o);
        }
        if (threadIdx.x == 0) {
            float mu  = s  * (1.f / Dc);
            float var = s2 * (1.f / Dc) - mu * mu;
            smu = mu;
            srs = rsqrtf(var + 1e-5f);
        }
    }
    __syncthreads();
    const float mu = smu, rs = srs;
    #pragma unroll
    for (int t = 0; t < 3; t++) {
        int c = threadIdx.x + t * 256;
        float v = (v3[t] - mu) * rs * lg[c] + lb[c];
        __half h = __float2half_rn(v);
        g_ahi[(size_t)row * Dc + c] = h;
        g_alo[(size_t)row * Dc + c] = __float2half_rn(v - __half2float(h));
    }
}

// ---------------- 1b) fused setup: weight splits + pad zeroing ---------------
__global__ void setup_k(const float* __restrict__ wq, const float* __restrict__ wp)
{
    int i = blockIdx.x * 256 + threadIdx.x;
    if (i < E3c * Dc) {
        float v = wq[i] * WSCALE;
        __half h = __float2half_rn(v);
        g_wqhi[i] = h;
        g_wqlo[i] = __float2half_rn(v - __half2float(h));
    }
    if (i < Dc * Dc) {
        float v = wp[i] * WSCALE;
        __half h = __float2half_rn(v);
        g_wphi[i] = h;
        g_wplo[i] = __float2half_rn(v - __half2float(h));
    }
    if (i < PADR * HDc) {
        size_t off = (size_t)Bc * Hc * Nc * HDc + i;
        __half z = __float2half_rn(0.f);
        g_qh[off] = z; g_ql[off] = z;
        g_kh[off] = z; g_kl[off] = z;
        g_vh[off] = z; g_vl[off] = z;
    }
}

// ---------------- 2) mma.sync fp16 GEMM, 128x128, 2 CTA/SM (R13) -------------
// MODE 0 (3-product): QKV; epilogue: 1/256, RoPE, fp16 split -> g_q/k/v
// MODE 1 (2-product): out = O_fp16 @ (wp*256)^T / 256 + bias
template<int MODE>
__global__ __launch_bounds__(256, 2) void mma_gemm_k(
    const float* __restrict__ bias, float* __restrict__ outp)
{
    const __half* __restrict__ Ahi = (MODE == 0) ? g_ahi : g_oh;
    const __half* __restrict__ Alo = (MODE == 0) ? g_alo : g_oh;   // unused if MODE 1
    const __half* __restrict__ Bhi = (MODE == 0) ? g_wqhi : g_wphi;
    const __half* __restrict__ Blo = (MODE == 0) ? g_wqlo : g_wplo;

    extern __shared__ char smem[];
    const uint32_t sb = smem_u32(smem);
    const int tid  = threadIdx.x;
    const int wid  = tid >> 5;
    const int lane = tid & 31;
    const int wm = wid >> 2;
    const int wn = wid & 3;
    const int e0 = blockIdx.x * BN;
    const int m0 = blockIdx.y * BM;

    const __half* gA[4] = {
        Ahi + (size_t)m0 * Dc, Alo + (size_t)m0 * Dc,
        Bhi + (size_t)e0 * Dc, Blo + (size_t)e0 * Dc };

    auto load_stage = [&](int s, int k0) {
        const uint32_t stg = sb + s * STAGE_BYTES;
        #pragma unroll
        for (int arr = 0; arr < 4; arr++) {
            if (MODE == 1 && arr == 1) continue;
            #pragma unroll
            for (int i = 0; i < 2; i++) {
                int ci = tid + i * 256;
                int r = ci >> 2, c = ci & 3;
                cp16(stg + arr * ARR_BYTES + r * ROWB + c * 16,
                     gA[arr] + (size_t)r * Dc + k0 + c * 8);
            }
        }
        cp_commit();
    };

    float acc[4][4][4];
    #pragma unroll
    for (int i = 0; i < 4; i++)
        #pragma unroll
        for (int j = 0; j < 4; j++)
            #pragma unroll
            for (int q = 0; q < 4; q++) acc[i][j][q] = 0.f;

    const int a_row   = (lane & 7) + ((lane >> 3) & 1) * 8;
    const int a_chunk = (lane >> 4) & 1;
    const int b_row   = (lane & 7) + ((lane >> 4) & 1) * 8;
    const int b_chunk = (lane >> 3) & 1;

    load_stage(0, 0);

    for (int it = 0; it < NK; it++) {
        if (it + 1 < NK) load_stage((it + 1) & 1, (it + 1) * BK);
        if (it + 1 < NK) cp_wait<1>(); else cp_wait<0>();
        __syncthreads();

        const uint32_t stg = sb + (it & 1) * STAGE_BYTES;
        const uint32_t aHi = stg;
        const uint32_t aLo = stg + ARR_BYTES;
        const uint32_t bHi = stg + 2 * ARR_BYTES;
        const uint32_t bLo = stg + 3 * ARR_BYTES;

        #pragma unroll
        for (int k16 = 0; k16 < 2; k16++) {
            uint32_t ah[4][4], al[4][4], bh[2][4], bl[2][4];
            #pragma unroll
            for (int i = 0; i < 4; i++) {
                uint32_t ro = (uint32_t)((wm * 64 + i * 16 + a_row) * ROWB
                                         + (k16 * 2 + a_chunk) * 16);
                LDM4(ah[i][0], ah[i][1], ah[i][2], ah[i][3], aHi + ro);
                if (MODE == 0) {
                    LDM4(al[i][0], al[i][1], al[i][2], al[i][3], aLo + ro);
                }
            }
            #pragma unroll
            for (int j2 = 0; j2 < 2; j2++) {
                uint32_t ro = (uint32_t)((wn * 32 + j2 * 16 + b_row) * ROWB
                                         + (k16 * 2 + b_chunk) * 16);
                LDM4(bh[j2][0], bh[j2][1], bh[j2][2], bh[j2][3], bHi + ro);
                LDM4(bl[j2][0], bl[j2][1], bl[j2][2], bl[j2][3], bLo + ro);
            }
            #pragma unroll
            for (int i = 0; i < 4; i++) {
                #pragma unroll
                for (int j = 0; j < 4; j++) {
                    uint32_t h0 = bh[j >> 1][(j & 1) * 2];
                    uint32_t h1 = bh[j >> 1][(j & 1) * 2 + 1];
                    uint32_t l0 = bl[j >> 1][(j & 1) * 2];
                    uint32_t l1 = bl[j >> 1][(j & 1) * 2 + 1];
                    MMA16816(acc[i][j], ah[i], h0, h1);
                    MMA16816(acc[i][j], ah[i], l0, l1);
                    if (MODE == 0) {
                        MMA16816(acc[i][j], al[i], h0, h1);
                    }
                }
            }
        }
        __syncthreads();
    }

    // ---- epilogue ----
    const int gid = lane >> 2, tig = lane & 3;
    if (MODE == 1) {
        #pragma unroll
        for (int i = 0; i < 4; i++) {
            #pragma unroll
            for (int j = 0; j < 4; j++) {
                int col  = e0 + wn * 32 + j * 8 + tig * 2;
                int row0 = m0 + wm * 64 + i * 16 + gid;
                int row1 = row0 + 8;
                float2 bz = *(const float2*)(bias + col);
                float2 v0 = make_float2(acc[i][j][0] * INVW + bz.x, acc[i][j][1] * INVW + bz.y);
                float2 v1 = make_float2(acc[i][j][2] * INVW + bz.x, acc[i][j][3] * INVW + bz.y);
                if (row0 < Mc) *(float2*)(outp + (size_t)row0 * Dc + col) = v0;
                if (row1 < Mc) *(float2*)(outp + (size_t)row1 * Dc + col) = v1;
            }
        }
    } else {
        const int which = e0 / Dc;
        __half* dH = (which == 0) ? g_qh : (which == 1) ? g_kh : g_vh;
        __half* dL = (which == 0) ? g_ql : (which == 1) ? g_kl : g_vl;
        #pragma unroll
        for (int i = 0; i < 4; i++) {
            #pragma unroll
            for (int j = 0; j < 4; j++) {
                int col = e0 + wn * 32 + j * 8 + tig * 2;
                int rem = col - which * Dc;
                int h = rem >> 6, d = rem & 63;
                int f = (d >> 1) & 15;
                float invf = expf(-(float)f * 0.5756462732485114f);
                #pragma unroll
                for (int rr = 0; rr < 2; rr++) {
                    int row = m0 + wm * 64 + i * 16 + gid + rr * 8;
                    if (row >= Mc) continue;
                    int b = row / Nc, n = row - b * Nc;
                    float x0 = acc[i][j][rr * 2] * INVW, x1 = acc[i][j][rr * 2 + 1] * INVW;
                    float o0, o1;
                    if (which < 2) {
                        int pos = 0;
                        if (n != 0) {
                            int p = n - 1;
                            pos = (d < 32) ? (p >> 5) : (p & 31);
                        }
                        float sn, cs;
                        sincosf((float)pos * invf, &sn, &cs);
                        o0 = x0 * cs - x1 * sn;
                        o1 = x1 * cs + x0 * sn;
                    } else {
                        o0 = x0; o1 = x1;
                    }
                    size_t dst = (((size_t)(b * Hc + h)) * Nc + n) * HDc + d;
                    uint32_t hp, lp;
                    split_pair(o0, o1, hp, lp);
                    *(uint32_t*)(dH + dst) = hp;
                    *(uint32_t*)(dL + dst) = lp;
                }
            }
        }
    }
}

// ---------------- 3) Flash attention: 12 warps, AQ=192, 3-stage KV -----------
__global__ __launch_bounds__(ATHREADS, 1) void attn2_k()
{
    extern __shared__ char sm[];
    const uint32_t sb = smem_u32(sm);
    const int tid = threadIdx.x, wid = tid >> 5, lane = tid & 31;
    const int bh = blockIdx.x, q0 = blockIdx.y * AQ;
    const int bI = bh / Hc, hI = bh % Hc;
    const size_t hb = (size_t)bh * Nc * HDc;
    const uint32_t Qh = sb + 3 * KVSTAGE, Ql = Qh + QARR;

    auto load_kv = [&](int s, int kt) {
        uint32_t st = sb + s * KVSTAGE;
        const size_t kb = hb + (size_t)kt * 64 * HDc;
        #pragma unroll
        for (int t = 0; t < 2; t++) {
            int idx = tid + t * ATHREADS;
            if (idx < 512) {
                int r = idx >> 3, c = idx & 7;
                size_t go = kb + (size_t)r * HDc + c * 8;
                cp16(swz(st,             r, c), g_kh + go);
                cp16(swz(st +     KVARR, r, c), g_kl + go);
                cp16(swz(st + 2 * KVARR, r, c), g_vh + go);
                cp16(swz(st + 3 * KVARR, r, c), g_vl + go);
            }
        }
        cp_commit();
    };

    // group 0: Q tile + KV stage 0
    {
        const __half* qhp = g_qh + hb + (size_t)q0 * HDc;
        const __half* qlp = g_ql + hb + (size_t)q0 * HDc;
        #pragma unroll
        for (int t = 0; t < 4; t++) {
            int idx = tid + t * ATHREADS;   // 0..1535
            int r = idx >> 3, c = idx & 7;
            cp16(swz(Qh, r, c), qhp + (size_t)r * HDc + c * 8);
            cp16(swz(Ql, r, c), qlp + (size_t)r * HDc + c * 8);
        }
        // KV stage 0 in same group
        {
            const size_t kb = hb;
            #pragma unroll
            for (int t = 0; t < 2; t++) {
                int idx = tid + t * ATHREADS;
                if (idx < 512) {
                    int r = idx >> 3, c = idx & 7;
                    size_t go = kb + (size_t)r * HDc + c * 8;
                    cp16(swz(sb,             r, c), g_kh + go);
                    cp16(swz(sb +     KVARR, r, c), g_kl + go);
                    cp16(swz(sb + 2 * KVARR, r, c), g_vh + go);
                    cp16(swz(sb + 3 * KVARR, r, c), g_vl + go);
                }
            }
        }
        cp_commit();
    }
    load_kv(1, 1);      // group 1: KV stage 1

    cp_wait<1>();       // group 0 (Q + KV0) done
    __syncthreads();
    uint32_t qh[4][4], ql[4][4];
    #pragma unroll
    for (int c = 0; c < 4; c++) {
        int row = wid * 16 + (lane & 15);
        int ch  = c * 2 + (lane >> 4);
        LDM4(qh[c][0], qh[c][1], qh[c][2], qh[c][3], swz(Qh, row, ch));
        LDM4(ql[c][0], ql[c][1], ql[c][2], ql[c][3], swz(Ql, row, ch));
    }

    float out[8][4];
    #pragma unroll
    for (int i = 0; i < 8; i++)
        #pragma unroll
        for (int q = 0; q < 4; q++) out[i][q] = 0.f;
    float m0 = -1e30f, m1 = -1e30f, l0 = 0.f, l1 = 0.f;

    const int NT = (Nc + 63) / 64;   // 17
    for (int kt = 0; kt < NT; kt++) {
        if (kt + 2 < NT) load_kv((kt + 2) % 3, kt + 2);
        if (kt + 2 < NT)      cp_wait<2>();
        else if (kt + 1 < NT) cp_wait<1>();
        else                  cp_wait<0>();
        __syncthreads();
        const uint32_t st = sb + (kt % 3) * KVSTAGE;
        const uint32_t Kh = st, Kl = st + KVARR, Vh = st + 2 * KVARR, Vl = st + 3 * KVARR;

        float sac[8][4];
        #pragma unroll
        for (int i = 0; i < 8; i++)
            #pragma unroll
            for (int q = 0; q < 4; q++) sac[i][q] = 0.f;
        #pragma unroll
        for (int c = 0; c < 4; c++) {
            #pragma unroll
            for (int g = 0; g < 4; g++) {
                int row = g * 16 + (lane & 15);
                int ch  = c * 2 + (lane >> 4);
                uint32_t kh0, kh1, kh2, kh3, kl0, kl1, kl2, kl3;
                LDM4(kh0, kh1, kh2, kh3, swz(Kh, row, ch));
                LDM4(kl0, kl1, kl2, kl3, swz(Kl, row, ch));
                MMA16816(sac[2 * g],     qh[c], kh0, kh2);
                MMA16816(sac[2 * g],     qh[c], kl0, kl2);
                MMA16816(sac[2 * g],     ql[c], kh0, kh2);
                MMA16816(sac[2 * g + 1], qh[c], kh1, kh3);
                MMA16816(sac[2 * g + 1], qh[c], kl1, kl3);
                MMA16816(sac[2 * g + 1], ql[c], kh1, kh3);
            }
        }
        const int k0 = kt * 64;
        #pragma unroll
        for (int j = 0; j < 8; j++) {
            sac[j][0] *= 0.125f; sac[j][1] *= 0.125f;
            sac[j][2] *= 0.125f; sac[j][3] *= 0.125f;
            int kc = k0 + j * 8 + 2 * (lane & 3);
            if (kc     >= Nc) { sac[j][0] = -1e30f; sac[j][2] = -1e30f; }
            if (kc + 1 >= Nc) { sac[j][1] = -1e30f; sac[j][3] = -1e30f; }
        }
        float mx0 = -1e30f, mx1 = -1e30f;
        #pragma unroll
        for (int j = 0; j < 8; j++) {
            mx0 = fmaxf(mx0, fmaxf(sac[j][0], sac[j][1]));
            mx1 = fmaxf(mx1, fmaxf(sac[j][2], sac[j][3]));
        }
        mx0 = fmaxf(mx0, __shfl_xor_sync(0xffffffffu, mx0, 1));
        mx0 = fmaxf(mx0, __shfl_xor_sync(0xffffffffu, mx0, 2));
        mx1 = fmaxf(mx1, __shfl_xor_sync(0xffffffffu, mx1, 1));
        mx1 = fmaxf(mx1, __shfl_xor_sync(0xffffffffu, mx1, 2));
        float mn0 = fmaxf(m0, mx0), mn1 = fmaxf(m1, mx1);
        float co0 = __expf(m0 - mn0), co1 = __expf(m1 - mn1);
        m0 = mn0; m1 = mn1;
        float rs0 = 0.f, rs1 = 0.f;
        #pragma unroll
        for (int j = 0; j < 8; j++) {
            sac[j][0] = __expf(sac[j][0] - mn0);
            sac[j][1] = __expf(sac[j][1] - mn0);
            sac[j][2] = __expf(sac[j][2] - mn1);
            sac[j][3] = __expf(sac[j][3] - mn1);
            rs0 += sac[j][0] + sac[j][1];
            rs1 += sac[j][2] + sac[j][3];
        }
        rs0 += __shfl_xor_sync(0xffffffffu, rs0, 1);
        rs0 += __shfl_xor_sync(0xffffffffu, rs0, 2);
        rs1 += __shfl_xor_sync(0xffffffffu, rs1, 1);
        rs1 += __shfl_xor_sync(0xffffffffu, rs1, 2);
        l0 = l0 * co0 + rs0;
        l1 = l1 * co1 + rs1;
        #pragma unroll
        for (int jd = 0; jd < 8; jd++) {
            out[jd][0] *= co0; out[jd][1] *= co0;
            out[jd][2] *= co1; out[jd][3] *= co1;
        }
        #pragma unroll
        for (int kc2 = 0; kc2 < 4; kc2++) {
            uint32_t AH[4];
            AH[0] = pack_h2(sac[2 * kc2][0],     sac[2 * kc2][1]);
            AH[1] = pack_h2(sac[2 * kc2][2],     sac[2 * kc2][3]);
            AH[2] = pack_h2(sac[2 * kc2 + 1][0], sac[2 * kc2 + 1][1]);
            AH[3] = pack_h2(sac[2 * kc2 + 1][2], sac[2 * kc2 + 1][3]);
            #pragma unroll
            for (int jd = 0; jd < 4; jd++) {
                int row = kc2 * 16 + (lane & 15);
                int ch  = jd * 2 + (lane >> 4);
                uint32_t v0, v1, v2, v3, w0, w1, w2, w3;
                LDM4T(v0, v1, v2, v3, swz(Vh, row, ch));
                LDM4T(w0, w1, w2, w3, swz(Vl, row, ch));
                MMA16816(out[2 * jd],     AH, v0, v1);
                MMA16816(out[2 * jd],     AH, w0, w1);
                MMA16816(out[2 * jd + 1], AH, v2, v3);
                MMA16816(out[2 * jd + 1], AH, w2, w3);
            }
        }
        __syncthreads();
    }
    const float inv0 = 1.f / l0, inv1 = 1.f / l1;
    const int r = q0 + wid * 16 + (lane >> 2);
    #pragma unroll
    for (int jd = 0; jd < 8; jd++) {
        int col = hI * 64 + jd * 8 + 2 * (lane & 3);
        if (r < Nc) {
            size_t mi = ((size_t)(bI * Nc + r)) * Dc + col;
            *(uint32_t*)(g_oh + mi) = pack_h2(out[jd][0] * inv0, out[jd][1] * inv0);
        }
        if (r + 8 < Nc) {
            size_t mi = ((size_t)(bI * Nc + r + 8)) * Dc + col;
            *(uint32_t*)(g_oh + mi) = pack_h2(out[jd][2] * inv1, out[jd][3] * inv1);
        }
    }
}

// ---------------- launch ------------------------------------------------------
extern "C" void kernel_launch(void* const* d_in, const int* in_sizes, int n_in,
                              void* d_out, int out_size)
{
    const float* x  = (const float*)d_in[0];
    const float* lg = (const float*)d_in[1];
    const float* lb = (const float*)d_in[2];
    const float* wq = (const float*)d_in[3];
    const float* wp = (const float*)d_in[4];
    const float* bp = (const float*)d_in[5];
    float* out = (float*)d_out;
    (void)in_sizes; (void)n_in; (void)out_size;

    cudaFuncSetAttribute(mma_gemm_k<0>, cudaFuncAttributeMaxDynamicSharedMemorySize, GEMM_SMEM);
    cudaFuncSetAttribute(mma_gemm_k<1>, cudaFuncAttributeMaxDynamicSharedMemorySize, GEMM_SMEM);
    cudaFuncSetAttribute(attn2_k, cudaFuncAttributeMaxDynamicSharedMemorySize, ATTN_SMEM);

    lnsplit_k<<<Mc, 256>>>(x, lg, lb);
    setup_k<<<(E3c * Dc + 255) / 256, 256>>>(wq, wp);
    mma_gemm_k<0><<<dim3(E3c / BN, MP / BM), 256, GEMM_SMEM>>>(nullptr, nullptr);
    attn2_k<<<dim3(Bc * Hc, (Nc + AQ - 1) / AQ), ATHREADS, ATTN_SMEM>>>();
    mma_gemm_k<1><<<dim3(Dc / BN, MP / BM), 256, GEMM_SMEM>>>(bp, out);
}